// round 16
// baseline (speedup 1.0000x reference)
#include <cuda_runtime.h>
#include <cstdint>

// ---------------------------------------------------------------------------
// B=8, N=128, S=100, F1=160
// Conv stack per image (1024 images):
//   L1: 1ch 100x100 -> conv3 98 -> pool 49  [2 bands/img, og-split]
//   L2: 10ch 49x49  -> conv3 47 -> pool 23  [2 bands/img, og-split]
//   L3+L4 fused -> 160 features
// ---------------------------------------------------------------------------

#define NIMG 1024

__device__ float g_P1[NIMG * 10 * 49 * 49];
__device__ float g_P2[NIMG * 10 * 23 * 23];
__device__ float g_Hf [NIMG * 160];
__device__ float g_dk1[NIMG * 256];
__device__ float g_dkf[NIMG * 512];
__device__ float g_xx [NIMG];
__device__ float g_XY [8 * 128 * 128];   // Gram -> overwritten with normalized K
__device__ float g_avg[NIMG * 160];
__device__ float g_H2 [NIMG * 160];
__device__ float g_H4 [NIMG * 160];
__device__ float g_H6 [NIMG * 160];

// ---------------------------------------------------------------------------
// L1: paired conv, 2 row-bands, og-split (R14 measured-best: -1.6us vs mono).
// ---------------------------------------------------------------------------
__global__ __launch_bounds__(160, 4)
void conv1_rows(const float* __restrict__ in,
                const float* __restrict__ w,
                const float* __restrict__ bias,
                float* __restrict__ out)
{
    constexpr int IS = 100, OS = 49, PW = 25, NR0 = 25;

    const int half = blockIdx.y;
    const int oy0 = half ? NR0 : 0;
    const int nr  = half ? (OS - NR0) : NR0;     // 24 : 25
    const int inRows = 2 * nr + 2;               // 50 : 52

    extern __shared__ float smem[];
    float* sIn = smem;                           // up to 52*100
    float* sW  = smem + 52 * 100;
    float* sB  = sW + 90;

    const int img = blockIdx.x;
    const float* gIn = in + (size_t)img * IS * IS + (size_t)(2 * oy0) * IS;
    const int total = inRows * IS;
    for (int i = threadIdx.x; i < total; i += 160) sIn[i] = gIn[i];
    for (int i = threadIdx.x; i < 90; i += 160) sW[i] = w[i];
    if (threadIdx.x < 10) sB[threadIdx.x] = bias[threadIdx.x];
    __syncthreads();

    const int ITEMS = nr * PW;
    for (int item = threadIdx.x; item < ITEMS; item += 160) {
        const int oyr = item / PW;
        const int px  = item % PW;
        const int iy0 = 2 * oyr;
        const int ix0 = 4 * px;
        const int oy  = oy0 + oyr;

        #pragma unroll 1
        for (int og = 0; og < 2; ++og) {
            float acc[2][4][5];
            #pragma unroll
            for (int oc = 0; oc < 5; ++oc) {
                const float bv = sB[og * 5 + oc];
                #pragma unroll
                for (int dy = 0; dy < 2; ++dy)
                    #pragma unroll
                    for (int dx = 0; dx < 4; ++dx) acc[dy][dx][oc] = bv;
            }

            const float* rp = sIn + iy0 * IS + ix0;
            float v[4][6];
            #pragma unroll
            for (int r = 0; r < 4; ++r)
                #pragma unroll
                for (int c = 0; c < 6; ++c) v[r][c] = rp[r * IS + c];

            const float* wp = sW + (og * 5) * 9;
            #pragma unroll
            for (int ky = 0; ky < 3; ++ky)
                #pragma unroll
                for (int kx = 0; kx < 3; ++kx)
                    #pragma unroll
                    for (int oc = 0; oc < 5; ++oc) {
                        const float wv = wp[oc * 9 + ky * 3 + kx];
                        #pragma unroll
                        for (int dy = 0; dy < 2; ++dy)
                            #pragma unroll
                            for (int dx = 0; dx < 4; ++dx)
                                acc[dy][dx][oc] += wv * v[ky + dy][kx + dx];
                    }

            #pragma unroll
            for (int j = 0; j < 2; ++j) {
                const int ox = 2 * px + j;
                if (ox >= OS) break;
                #pragma unroll
                for (int oc = 0; oc < 5; ++oc) {
                    float m = fmaxf(fmaxf(acc[0][2 * j][oc], acc[0][2 * j + 1][oc]),
                                    fmaxf(acc[1][2 * j][oc], acc[1][2 * j + 1][oc]));
                    out[((size_t)img * 10 + og * 5 + oc) * (OS * OS) + oy * OS + ox]
                        = fmaxf(m, 0.0f);
                }
            }
        }
    }
}

// ---------------------------------------------------------------------------
// L2: direct paired conv, 2 row-bands, og-split (FROZEN measured-best).
// ---------------------------------------------------------------------------
template<int IC, int IS, int BD>
__global__ __launch_bounds__(BD, 4)
void conv_pool_rows(const float* __restrict__ in,
                    const float* __restrict__ w,
                    const float* __restrict__ bias,
                    float* __restrict__ out)
{
    constexpr int OS = (IS - 2) / 2;    // 23
    constexpr int PW = (OS + 1) / 2;    // 12
    constexpr int WE = 10 * IC * 9;
    constexpr int NR0 = (OS + 1) / 2;   // 12

    const int half = blockIdx.y;
    const int oy0 = half ? NR0 : 0;
    const int nr  = half ? (OS - NR0) : NR0;
    const int inRows = 2 * nr + 2;

    extern __shared__ float smem[];
    float* sIn = smem;
    float* sW  = smem + IC * (2 * NR0 + 2) * IS;
    float* sB  = sW + WE;

    const int img = blockIdx.x;
    const int icStride = inRows * IS;
    const float* gIn = in + (size_t)img * IC * IS * IS + (size_t)(2 * oy0) * IS;

    const int total = IC * icStride;
    for (int i = threadIdx.x; i < total; i += BD) {
        const int ic = i / icStride;
        sIn[i] = gIn[ic * IS * IS + (i - ic * icStride)];
    }
    for (int i = threadIdx.x; i < WE; i += BD) sW[i] = w[i];
    if (threadIdx.x < 10) sB[threadIdx.x] = bias[threadIdx.x];
    __syncthreads();

    const int ITEMS = nr * PW;
    for (int item = threadIdx.x; item < ITEMS; item += BD) {
        const int oyr = item / PW;
        const int px  = item % PW;
        const int iy0 = 2 * oyr;
        const int ix0 = 4 * px;
        const int oy  = oy0 + oyr;

        #pragma unroll 1
        for (int og = 0; og < 2; ++og) {
            float acc[2][4][5];
            #pragma unroll
            for (int oc = 0; oc < 5; ++oc) {
                const float bv = sB[og * 5 + oc];
                #pragma unroll
                for (int dy = 0; dy < 2; ++dy)
                    #pragma unroll
                    for (int dx = 0; dx < 4; ++dx) acc[dy][dx][oc] = bv;
            }

            #pragma unroll 1
            for (int ic = 0; ic < IC; ++ic) {
                const float* rp = sIn + ic * icStride + iy0 * IS + ix0;
                float v[4][6];
                #pragma unroll
                for (int r = 0; r < 4; ++r)
                    #pragma unroll
                    for (int c = 0; c < 6; ++c) v[r][c] = rp[r * IS + c];

                const float* wp = sW + (og * 5) * IC * 9 + ic * 9;
                #pragma unroll
                for (int ky = 0; ky < 3; ++ky)
                    #pragma unroll
                    for (int kx = 0; kx < 3; ++kx)
                        #pragma unroll
                        for (int oc = 0; oc < 5; ++oc) {
                            const float wv = wp[oc * IC * 9 + ky * 3 + kx];
                            #pragma unroll
                            for (int dy = 0; dy < 2; ++dy)
                                #pragma unroll
                                for (int dx = 0; dx < 4; ++dx)
                                    acc[dy][dx][oc] += wv * v[ky + dy][kx + dx];
                        }
            }

            #pragma unroll
            for (int j = 0; j < 2; ++j) {
                const int ox = 2 * px + j;
                if (ox >= OS) break;
                #pragma unroll
                for (int oc = 0; oc < 5; ++oc) {
                    float m = fmaxf(fmaxf(acc[0][2 * j][oc], acc[0][2 * j + 1][oc]),
                                    fmaxf(acc[1][2 * j][oc], acc[1][2 * j + 1][oc]));
                    out[((size_t)img * 10 + og * 5 + oc) * (OS * OS) + oy * OS + ox]
                        = fmaxf(m, 0.0f);
                }
            }
        }
    }
}

// ---------------------------------------------------------------------------
// Fused L3 + L4 (FROZEN measured-best).
// ---------------------------------------------------------------------------
template<int G, int BD>
__global__ __launch_bounds__(BD, 4)
void conv34_fused(const float* __restrict__ in,
                  const float* __restrict__ w3,
                  const float* __restrict__ b3,
                  const float* __restrict__ w4,
                  const float* __restrict__ b4,
                  float* __restrict__ out)
{
    constexpr int IS = 23, OS = 10, PW = 5;
    constexpr int IN = 10 * IS * IS;
    constexpr int MID = 10 * OS * OS;

    extern __shared__ float smem[];
    float* sIn  = smem;
    float* sW3  = sIn + G * IN;
    float* sB3  = sW3 + 900;
    float* sMid = sB3 + 10;
    float* sW4  = sMid + G * MID;
    float* sB4  = sW4 + 900;

    const int img0 = blockIdx.x * G;
    for (int i = threadIdx.x; i < G * IN; i += BD) {
        const int g = i / IN;
        sIn[i] = in[(size_t)(img0 + g) * IN + (i - g * IN)];
    }
    for (int i = threadIdx.x; i < 900; i += BD) { sW3[i] = w3[i]; sW4[i] = w4[i]; }
    if (threadIdx.x < 10) { sB3[threadIdx.x] = b3[threadIdx.x];
                            sB4[threadIdx.x] = b4[threadIdx.x]; }
    __syncthreads();

    for (int item = threadIdx.x; item < G * OS * PW; item += BD) {
        const int g   = item / (OS * PW);
        const int rem = item - g * (OS * PW);
        const int oy  = rem / PW;
        const int px  = rem % PW;
        const int iy0 = 2 * oy, ix0 = 4 * px;
        const float* base = sIn + g * IN;
        float* mid = sMid + g * MID;

        #pragma unroll 1
        for (int og = 0; og < 2; ++og) {
            float acc[2][4][5];
            #pragma unroll
            for (int oc = 0; oc < 5; ++oc) {
                const float bv = sB3[og * 5 + oc];
                #pragma unroll
                for (int dy = 0; dy < 2; ++dy)
                    #pragma unroll
                    for (int dx = 0; dx < 4; ++dx) acc[dy][dx][oc] = bv;
            }

            #pragma unroll 1
            for (int ic = 0; ic < 10; ++ic) {
                const float* rp = base + ic * IS * IS + iy0 * IS + ix0;
                float v[4][6];
                #pragma unroll
                for (int r = 0; r < 4; ++r)
                    #pragma unroll
                    for (int c = 0; c < 6; ++c) v[r][c] = rp[r * IS + c];

                const float* wp = sW3 + (og * 5) * 90 + ic * 9;
                #pragma unroll
                for (int ky = 0; ky < 3; ++ky)
                    #pragma unroll
                    for (int kx = 0; kx < 3; ++kx)
                        #pragma unroll
                        for (int oc = 0; oc < 5; ++oc) {
                            const float wv = wp[oc * 90 + ky * 3 + kx];
                            #pragma unroll
                            for (int dy = 0; dy < 2; ++dy)
                                #pragma unroll
                                for (int dx = 0; dx < 4; ++dx)
                                    acc[dy][dx][oc] += wv * v[ky + dy][kx + dx];
                        }
            }

            #pragma unroll
            for (int j = 0; j < 2; ++j) {
                const int ox = 2 * px + j;
                #pragma unroll
                for (int oc = 0; oc < 5; ++oc) {
                    float m = fmaxf(fmaxf(acc[0][2 * j][oc], acc[0][2 * j + 1][oc]),
                                    fmaxf(acc[1][2 * j][oc], acc[1][2 * j + 1][oc]));
                    mid[(og * 5 + oc) * (OS * OS) + oy * OS + ox] = fmaxf(m, 0.0f);
                }
            }
        }
    }
    __syncthreads();

    for (int item = threadIdx.x; item < G * 16; item += BD) {
        const int g   = item / 16;
        const int pix = item % 16;
        const int oy  = pix / 4, ox = pix % 4;
        const float* mid = sMid + g * MID;

        #pragma unroll 1
        for (int og = 0; og < 2; ++og) {
            float acc[2][2][5];
            #pragma unroll
            for (int oc = 0; oc < 5; ++oc) {
                const float bv = sB4[og * 5 + oc];
                acc[0][0][oc] = bv; acc[0][1][oc] = bv;
                acc[1][0][oc] = bv; acc[1][1][oc] = bv;
            }

            #pragma unroll 1
            for (int ic = 0; ic < 10; ++ic) {
                const float* rp = mid + ic * (OS * OS) + 2 * oy * OS + 2 * ox;
                float v[4][4];
                #pragma unroll
                for (int r = 0; r < 4; ++r)
                    #pragma unroll
                    for (int c = 0; c < 4; ++c) v[r][c] = rp[r * OS + c];

                const float* wp = sW4 + (og * 5) * 90 + ic * 9;
                #pragma unroll
                for (int ky = 0; ky < 3; ++ky)
                    #pragma unroll
                    for (int kx = 0; kx < 3; ++kx)
                        #pragma unroll
                        for (int oc = 0; oc < 5; ++oc) {
                            const float wv = wp[oc * 90 + ky * 3 + kx];
                            #pragma unroll
                            for (int dy = 0; dy < 2; ++dy)
                                #pragma unroll
                                for (int dx = 0; dx < 2; ++dx)
                                    acc[dy][dx][oc] += wv * v[ky + dy][kx + dx];
                        }
            }

            #pragma unroll
            for (int oc = 0; oc < 5; ++oc) {
                float m = fmaxf(fmaxf(acc[0][0][oc], acc[0][1][oc]),
                                fmaxf(acc[1][0][oc], acc[1][1][oc]));
                out[(size_t)(img0 + g) * 160 + (og * 5 + oc) * 16 + pix]
                    = fmaxf(m, 0.0f);
            }
        }
    }
}

// ---------------------------------------------------------------------------
// Double-buffered SGEMM-NT (FROZEN: dense TM=4/BD=128, xy TM=2/BD=256).
// ---------------------------------------------------------------------------
template<int TM, int BD, bool TANH, bool HASBIAS, bool DIAG>
__global__ __launch_bounds__(BD)
void gemmV(const float* __restrict__ A, const float* __restrict__ B,
           const float* __restrict__ bias, float* __restrict__ C,
           float* __restrict__ xxOut,
           int M, int N, int K,
           long long sA, long long sB, long long sC)
{
    constexpr int TN = 2;
    constexpr int TX = 32 / TN;
    constexpr int NLD = 512 / BD;
    __shared__ float As[32][36];
    __shared__ float Bs[32][36];

    const int tid = threadIdx.x;
    const int ty = tid / TX;
    const int tx = tid % TX;

    const int row0 = blockIdx.y * 32;
    const int col0 = blockIdx.x * 32;
    const float* Ab = A + blockIdx.z * sA + (size_t)row0 * K;
    const float* Bb = B + blockIdx.z * sB + (size_t)col0 * K;
    float* Cb = C + blockIdx.z * sC;

    float acc[TM][TN] = {};
    float4 pre[NLD];

    #pragma unroll
    for (int l = 0; l < NLD; ++l) {
        const int i = tid + l * BD;
        const int idx = i & 255;
        const float* src = ((i < 256) ? Ab : Bb)
                         + (size_t)(idx >> 3) * K + (idx & 7) * 4;
        pre[l] = *(const float4*)src;
    }

    for (int k0 = 0; k0 < K; k0 += 32) {
        #pragma unroll
        for (int l = 0; l < NLD; ++l) {
            const int i = tid + l * BD;
            const int idx = i & 255;
            const int r = idx >> 3;
            const int q = idx & 7;
            float* dst = (i < 256) ? &As[q * 4][r] : &Bs[q * 4][r];
            dst[0 * 36] = pre[l].x; dst[1 * 36] = pre[l].y;
            dst[2 * 36] = pre[l].z; dst[3 * 36] = pre[l].w;
        }
        __syncthreads();

        if (k0 + 32 < K) {
            #pragma unroll
            for (int l = 0; l < NLD; ++l) {
                const int i = tid + l * BD;
                const int idx = i & 255;
                const float* src = ((i < 256) ? Ab : Bb)
                                 + (size_t)(idx >> 3) * K + k0 + 32 + (idx & 7) * 4;
                pre[l] = *(const float4*)src;
            }
        }

        #pragma unroll
        for (int kk = 0; kk < 32; ++kk) {
            float a[TM], b[TN];
            if (TM == 4) {
                const float4 t = *(const float4*)&As[kk][ty * 4];
                a[0] = t.x; a[1] = t.y; a[2] = t.z; a[3] = t.w;
            } else {
                const float2 t = *(const float2*)&As[kk][ty * 2];
                a[0] = t.x; a[1] = t.y;
            }
            {
                const float2 t = *(const float2*)&Bs[kk][tx * 2];
                b[0] = t.x; b[1] = t.y;
            }
            #pragma unroll
            for (int i = 0; i < TM; ++i)
                #pragma unroll
                for (int j = 0; j < TN; ++j)
                    acc[i][j] += a[i] * b[j];
        }
        __syncthreads();
    }

    #pragma unroll
    for (int i = 0; i < TM; ++i) {
        const int gr = row0 + ty * TM + i;
        #pragma unroll
        for (int j = 0; j < TN; ++j) {
            const int gc = col0 + tx * TN + j;
            float v = acc[i][j];
            if (HASBIAS) v += bias[gc];
            if (TANH) v = tanhf(v);
            Cb[(size_t)gr * N + gc] = v;
            if (DIAG && gr == gc)
                xxOut[blockIdx.z * 128 + gr] = v;
        }
    }
}

// ---------------------------------------------------------------------------
// Fused softmax + message-pass + residual average.
// COMPUTE_K=true  (round 1): build K, normalize, persist to xy.
// COMPUTE_K=false (rounds 2,3): load precomputed K. Bit-identical K.
// ---------------------------------------------------------------------------
template<bool COMPUTE_K>
__global__ void mix_avg_sm_kernel(float* __restrict__ xy,
                                  const float* __restrict__ xx,
                                  const float* __restrict__ sigma,
                                  const float* __restrict__ z,
                                  float* __restrict__ out)
{
    const int b  = blockIdx.y;
    const int n0 = blockIdx.x * 8;
    const int t  = threadIdx.x;

    __shared__ float sK[8][128];
    __shared__ float sSum[8];

    float* xyr = xy + ((size_t)b * 128 + n0) * 128;

    if (COMPUTE_K) {
        const float inv_s = 1.0f / sigma[0];
        const float* xxb = xx + b * 128;
        for (int i = t; i < 8 * 128; i += 160) {
            const int m = i & 127;
            sK[i >> 7][m] = (2.0f * xyr[i] - xxb[m]) * inv_s;
        }
        __syncthreads();

        if (t < 128) {
            const int r = t >> 4;
            const int s = t & 15;
            float mx = -3.0e38f;
            #pragma unroll
            for (int m = s; m < 128; m += 16) mx = fmaxf(mx, sK[r][m]);
            #pragma unroll
            for (int o = 8; o > 0; o >>= 1)
                mx = fmaxf(mx, __shfl_down_sync(0xFFFFFFFFu, mx, o, 16));
            mx = __shfl_sync(0xFFFFFFFFu, mx, 0, 16);

            float sum = 0.0f;
            #pragma unroll
            for (int m = s; m < 128; m += 16) {
                const float e = expf(sK[r][m] - mx);
                sK[r][m] = e;
                sum += e;
            }
            #pragma unroll
            for (int o = 8; o > 0; o >>= 1)
                sum += __shfl_down_sync(0xFFFFFFFFu, sum, o, 16);
            if (s == 0) sSum[r] = sum;
        }
        __syncthreads();

        if (t < 128) {
            const int r = t >> 4;
            const int s = t & 15;
            const float sum = sSum[r];
            #pragma unroll
            for (int m = s; m < 128; m += 16) sK[r][m] = sK[r][m] / sum;
        }
        __syncthreads();

        for (int i = t; i < 8 * 128; i += 160)
            xyr[i] = sK[i >> 7][i & 127];
    } else {
        for (int i = t; i < 8 * 128; i += 160)
            sK[i >> 7][i & 127] = xyr[i];
        __syncthreads();
    }

    const float* zb = z + (size_t)b * 128 * 160;
    float acc[8] = {};
    #pragma unroll 4
    for (int m = 0; m < 128; ++m) {
        const float zv = zb[(size_t)m * 160 + t];
        #pragma unroll
        for (int j = 0; j < 8; ++j) acc[j] += sK[j][m] * zv;
    }
    #pragma unroll
    for (int j = 0; j < 8; ++j)
        out[((size_t)b * 128 + n0 + j) * 160 + t] =
            0.5f * (acc[j] + zb[(size_t)(n0 + j) * 160 + t]);
}

// out[b] = exp( sum_d max_n(H6[b,n,d]) * Wc[d] + bc )
__global__ void final_kernel(const float* __restrict__ H6,
                             const float* __restrict__ Wc,
                             const float* __restrict__ bc,
                             float* __restrict__ out)
{
    const int b = blockIdx.x;
    const int t = threadIdx.x;
    float m = -3.0e38f;
    for (int n = 0; n < 128; ++n)
        m = fmaxf(m, H6[((size_t)b * 128 + n) * 160 + t]);
    float s = m * Wc[t];
    #pragma unroll
    for (int o = 16; o > 0; o >>= 1)
        s += __shfl_down_sync(0xFFFFFFFFu, s, o);
    __shared__ float red[5];
    if ((t & 31) == 0) red[t >> 5] = s;
    __syncthreads();
    if (t == 0) {
        float tot = red[0] + red[1] + red[2] + red[3] + red[4];
        out[b] = expf(tot + bc[0]);
    }
}

// ---------------------------------------------------------------------------
// Host launcher
// ---------------------------------------------------------------------------
extern "C" void kernel_launch(void* const* d_in, const int* in_sizes, int n_in,
                              void* d_out, int out_size)
{
    const float* H     = (const float*)d_in[0];
    const float* w1    = (const float*)d_in[1];
    const float* b1    = (const float*)d_in[2];
    const float* w2    = (const float*)d_in[3];
    const float* b2    = (const float*)d_in[4];
    const float* w3    = (const float*)d_in[5];
    const float* b3    = (const float*)d_in[6];
    const float* w4    = (const float*)d_in[7];
    const float* b4    = (const float*)d_in[8];
    const float* Wdk1  = (const float*)d_in[9];
    const float* bdk1  = (const float*)d_in[10];
    const float* Wdk2  = (const float*)d_in[11];
    const float* bdk2  = (const float*)d_in[12];
    const float* Wt1   = (const float*)d_in[13];
    const float* bt1   = (const float*)d_in[14];
    const float* Wt2   = (const float*)d_in[15];
    const float* bt2   = (const float*)d_in[16];
    const float* Wt3   = (const float*)d_in[17];
    const float* bt3   = (const float*)d_in[18];
    const float* sigma = (const float*)d_in[19];
    const float* Wc    = (const float*)d_in[20];
    const float* bc    = (const float*)d_in[21];

    float *p1, *p2, *hf, *dk1, *dkf, *xx, *xy, *avg, *h2, *h4, *h6;
    cudaGetSymbolAddress((void**)&p1,  g_P1);
    cudaGetSymbolAddress((void**)&p2,  g_P2);
    cudaGetSymbolAddress((void**)&hf,  g_Hf);
    cudaGetSymbolAddress((void**)&dk1, g_dk1);
    cudaGetSymbolAddress((void**)&dkf, g_dkf);
    cudaGetSymbolAddress((void**)&xx,  g_xx);
    cudaGetSymbolAddress((void**)&xy,  g_XY);
    cudaGetSymbolAddress((void**)&avg, g_avg);
    cudaGetSymbolAddress((void**)&h2,  g_H2);
    cudaGetSymbolAddress((void**)&h4,  g_H4);
    cudaGetSymbolAddress((void**)&h6,  g_H6);

    const size_t smem1 = (52 * 100 + 90 + 10) * sizeof(float);               // 21.2 KB
    const size_t smem2 = (10 * 26 * 49 + 900 + 10) * sizeof(float);          // 54.6 KB
    const size_t smemf = (2 * 10 * 23 * 23 + 900 + 10 + 2 * 1000 + 900 + 10)
                         * sizeof(float);                                     // 57.6 KB
    cudaFuncSetAttribute(conv_pool_rows<10, 49, 160>,
                         cudaFuncAttributeMaxDynamicSharedMemorySize, (int)smem2);
    cudaFuncSetAttribute(conv34_fused<2, 128>,
                         cudaFuncAttributeMaxDynamicSharedMemorySize, (int)smemf);

    // ---- Conv stack ----
    conv1_rows<<<dim3(NIMG, 2), 160, smem1>>>(H, w1, b1, p1);
    conv_pool_rows<10, 49, 160><<<dim3(NIMG, 2), 160, smem2>>>(p1, w2, b2, p2);
    conv34_fused<2, 128><<<NIMG / 2, 128, smemf>>>(p2, w3, b3, w4, b4, hf);

    // ---- Deep-kernel MLP ----
    gemmV<4, 128, true, true, false><<<dim3(8, 32), 128>>>(
        hf, Wdk1, bdk1, dk1, nullptr, 1024, 256, 160, 0, 0, 0);
    gemmV<4, 128, true, true, false><<<dim3(16, 32), 128>>>(
        dk1, Wdk2, bdk2, dkf, nullptr, 1024, 512, 256, 0, 0, 0);

    // ---- Gram matrix xy (+ diagonal -> xx); softmax fused into mix ----
    gemmV<2, 256, false, false, true><<<dim3(4, 4, 8), 256>>>(
        dkf, dkf, nullptr, xy, xx, 128, 128, 512,
        128LL * 512, 128LL * 512, 128LL * 128);

    dim3 mixg(16, 8);

    // ---- Round 1 (computes + persists K) ----
    mix_avg_sm_kernel<true><<<mixg, 160>>>(xy, xx, sigma, hf, avg);
    gemmV<4, 128, true, true, false><<<dim3(5, 32), 128>>>(
        avg, Wt1, bt1, h2, nullptr, 1024, 160, 160, 0, 0, 0);

    // ---- Round 2 (reuses K) ----
    mix_avg_sm_kernel<false><<<mixg, 160>>>(xy, xx, sigma, h2, avg);
    gemmV<4, 128, true, true, false><<<dim3(5, 32), 128>>>(
        avg, Wt2, bt2, h4, nullptr, 1024, 160, 160, 0, 0, 0);

    // ---- Round 3 (reuses K) ----
    mix_avg_sm_kernel<false><<<mixg, 160>>>(xy, xx, sigma, h4, avg);
    gemmV<4, 128, true, true, false><<<dim3(5, 32), 128>>>(
        avg, Wt3, bt3, h6, nullptr, 1024, 160, 160, 0, 0, 0);

    // ---- Finish ----
    final_kernel<<<8, 160>>>(h6, Wc, bc, (float*)d_out);
}

// round 17
// speedup vs baseline: 1.0099x; 1.0099x over previous
#include <cuda_runtime.h>
#include <cstdint>

// ---------------------------------------------------------------------------
// B=8, N=128, S=100, F1=160  — measured-best configuration (R14, 387.5us)
// Conv stack per image (1024 images):
//   L1: 1ch 100x100 -> conv3 98 -> pool 49  [2 bands/img, og-split]
//   L2: 10ch 49x49  -> conv3 47 -> pool 23  [2 bands/img, og-split]
//   L3+L4 fused -> 160 features
// Tail: TM=4/BD=128 double-buffered gemms, Gram-diag xx, fused softmax-mix.
// ---------------------------------------------------------------------------

#define NIMG 1024

__device__ float g_P1[NIMG * 10 * 49 * 49];
__device__ float g_P2[NIMG * 10 * 23 * 23];
__device__ float g_Hf [NIMG * 160];
__device__ float g_dk1[NIMG * 256];
__device__ float g_dkf[NIMG * 512];
__device__ float g_xx [NIMG];
__device__ float g_XY [8 * 128 * 128];   // raw Gram matrix
__device__ float g_avg[NIMG * 160];
__device__ float g_H2 [NIMG * 160];
__device__ float g_H4 [NIMG * 160];
__device__ float g_H6 [NIMG * 160];

// ---------------------------------------------------------------------------
// L1: paired conv, 2 row-bands, og-split (measured-best).
// ---------------------------------------------------------------------------
__global__ __launch_bounds__(160, 4)
void conv1_rows(const float* __restrict__ in,
                const float* __restrict__ w,
                const float* __restrict__ bias,
                float* __restrict__ out)
{
    constexpr int IS = 100, OS = 49, PW = 25, NR0 = 25;

    const int half = blockIdx.y;
    const int oy0 = half ? NR0 : 0;
    const int nr  = half ? (OS - NR0) : NR0;     // 24 : 25
    const int inRows = 2 * nr + 2;               // 50 : 52

    extern __shared__ float smem[];
    float* sIn = smem;                           // up to 52*100
    float* sW  = smem + 52 * 100;
    float* sB  = sW + 90;

    const int img = blockIdx.x;
    const float* gIn = in + (size_t)img * IS * IS + (size_t)(2 * oy0) * IS;
    const int total = inRows * IS;
    for (int i = threadIdx.x; i < total; i += 160) sIn[i] = gIn[i];
    for (int i = threadIdx.x; i < 90; i += 160) sW[i] = w[i];
    if (threadIdx.x < 10) sB[threadIdx.x] = bias[threadIdx.x];
    __syncthreads();

    const int ITEMS = nr * PW;
    for (int item = threadIdx.x; item < ITEMS; item += 160) {
        const int oyr = item / PW;
        const int px  = item % PW;
        const int iy0 = 2 * oyr;
        const int ix0 = 4 * px;
        const int oy  = oy0 + oyr;

        #pragma unroll 1
        for (int og = 0; og < 2; ++og) {
            float acc[2][4][5];
            #pragma unroll
            for (int oc = 0; oc < 5; ++oc) {
                const float bv = sB[og * 5 + oc];
                #pragma unroll
                for (int dy = 0; dy < 2; ++dy)
                    #pragma unroll
                    for (int dx = 0; dx < 4; ++dx) acc[dy][dx][oc] = bv;
            }

            const float* rp = sIn + iy0 * IS + ix0;
            float v[4][6];
            #pragma unroll
            for (int r = 0; r < 4; ++r)
                #pragma unroll
                for (int c = 0; c < 6; ++c) v[r][c] = rp[r * IS + c];

            const float* wp = sW + (og * 5) * 9;
            #pragma unroll
            for (int ky = 0; ky < 3; ++ky)
                #pragma unroll
                for (int kx = 0; kx < 3; ++kx)
                    #pragma unroll
                    for (int oc = 0; oc < 5; ++oc) {
                        const float wv = wp[oc * 9 + ky * 3 + kx];
                        #pragma unroll
                        for (int dy = 0; dy < 2; ++dy)
                            #pragma unroll
                            for (int dx = 0; dx < 4; ++dx)
                                acc[dy][dx][oc] += wv * v[ky + dy][kx + dx];
                    }

            #pragma unroll
            for (int j = 0; j < 2; ++j) {
                const int ox = 2 * px + j;
                if (ox >= OS) break;
                #pragma unroll
                for (int oc = 0; oc < 5; ++oc) {
                    float m = fmaxf(fmaxf(acc[0][2 * j][oc], acc[0][2 * j + 1][oc]),
                                    fmaxf(acc[1][2 * j][oc], acc[1][2 * j + 1][oc]));
                    out[((size_t)img * 10 + og * 5 + oc) * (OS * OS) + oy * OS + ox]
                        = fmaxf(m, 0.0f);
                }
            }
        }
    }
}

// ---------------------------------------------------------------------------
// L2: direct paired conv, 2 row-bands, og-split (FROZEN measured-best).
// ---------------------------------------------------------------------------
template<int IC, int IS, int BD>
__global__ __launch_bounds__(BD, 4)
void conv_pool_rows(const float* __restrict__ in,
                    const float* __restrict__ w,
                    const float* __restrict__ bias,
                    float* __restrict__ out)
{
    constexpr int OS = (IS - 2) / 2;    // 23
    constexpr int PW = (OS + 1) / 2;    // 12
    constexpr int WE = 10 * IC * 9;
    constexpr int NR0 = (OS + 1) / 2;   // 12

    const int half = blockIdx.y;
    const int oy0 = half ? NR0 : 0;
    const int nr  = half ? (OS - NR0) : NR0;
    const int inRows = 2 * nr + 2;

    extern __shared__ float smem[];
    float* sIn = smem;
    float* sW  = smem + IC * (2 * NR0 + 2) * IS;
    float* sB  = sW + WE;

    const int img = blockIdx.x;
    const int icStride = inRows * IS;
    const float* gIn = in + (size_t)img * IC * IS * IS + (size_t)(2 * oy0) * IS;

    const int total = IC * icStride;
    for (int i = threadIdx.x; i < total; i += BD) {
        const int ic = i / icStride;
        sIn[i] = gIn[ic * IS * IS + (i - ic * icStride)];
    }
    for (int i = threadIdx.x; i < WE; i += BD) sW[i] = w[i];
    if (threadIdx.x < 10) sB[threadIdx.x] = bias[threadIdx.x];
    __syncthreads();

    const int ITEMS = nr * PW;
    for (int item = threadIdx.x; item < ITEMS; item += BD) {
        const int oyr = item / PW;
        const int px  = item % PW;
        const int iy0 = 2 * oyr;
        const int ix0 = 4 * px;
        const int oy  = oy0 + oyr;

        #pragma unroll 1
        for (int og = 0; og < 2; ++og) {
            float acc[2][4][5];
            #pragma unroll
            for (int oc = 0; oc < 5; ++oc) {
                const float bv = sB[og * 5 + oc];
                #pragma unroll
                for (int dy = 0; dy < 2; ++dy)
                    #pragma unroll
                    for (int dx = 0; dx < 4; ++dx) acc[dy][dx][oc] = bv;
            }

            #pragma unroll 1
            for (int ic = 0; ic < IC; ++ic) {
                const float* rp = sIn + ic * icStride + iy0 * IS + ix0;
                float v[4][6];
                #pragma unroll
                for (int r = 0; r < 4; ++r)
                    #pragma unroll
                    for (int c = 0; c < 6; ++c) v[r][c] = rp[r * IS + c];

                const float* wp = sW + (og * 5) * IC * 9 + ic * 9;
                #pragma unroll
                for (int ky = 0; ky < 3; ++ky)
                    #pragma unroll
                    for (int kx = 0; kx < 3; ++kx)
                        #pragma unroll
                        for (int oc = 0; oc < 5; ++oc) {
                            const float wv = wp[oc * IC * 9 + ky * 3 + kx];
                            #pragma unroll
                            for (int dy = 0; dy < 2; ++dy)
                                #pragma unroll
                                for (int dx = 0; dx < 4; ++dx)
                                    acc[dy][dx][oc] += wv * v[ky + dy][kx + dx];
                        }
            }

            #pragma unroll
            for (int j = 0; j < 2; ++j) {
                const int ox = 2 * px + j;
                if (ox >= OS) break;
                #pragma unroll
                for (int oc = 0; oc < 5; ++oc) {
                    float m = fmaxf(fmaxf(acc[0][2 * j][oc], acc[0][2 * j + 1][oc]),
                                    fmaxf(acc[1][2 * j][oc], acc[1][2 * j + 1][oc]));
                    out[((size_t)img * 10 + og * 5 + oc) * (OS * OS) + oy * OS + ox]
                        = fmaxf(m, 0.0f);
                }
            }
        }
    }
}

// ---------------------------------------------------------------------------
// Fused L3 + L4 (FROZEN measured-best).
// ---------------------------------------------------------------------------
template<int G, int BD>
__global__ __launch_bounds__(BD, 4)
void conv34_fused(const float* __restrict__ in,
                  const float* __restrict__ w3,
                  const float* __restrict__ b3,
                  const float* __restrict__ w4,
                  const float* __restrict__ b4,
                  float* __restrict__ out)
{
    constexpr int IS = 23, OS = 10, PW = 5;
    constexpr int IN = 10 * IS * IS;
    constexpr int MID = 10 * OS * OS;

    extern __shared__ float smem[];
    float* sIn  = smem;
    float* sW3  = sIn + G * IN;
    float* sB3  = sW3 + 900;
    float* sMid = sB3 + 10;
    float* sW4  = sMid + G * MID;
    float* sB4  = sW4 + 900;

    const int img0 = blockIdx.x * G;
    for (int i = threadIdx.x; i < G * IN; i += BD) {
        const int g = i / IN;
        sIn[i] = in[(size_t)(img0 + g) * IN + (i - g * IN)];
    }
    for (int i = threadIdx.x; i < 900; i += BD) { sW3[i] = w3[i]; sW4[i] = w4[i]; }
    if (threadIdx.x < 10) { sB3[threadIdx.x] = b3[threadIdx.x];
                            sB4[threadIdx.x] = b4[threadIdx.x]; }
    __syncthreads();

    for (int item = threadIdx.x; item < G * OS * PW; item += BD) {
        const int g   = item / (OS * PW);
        const int rem = item - g * (OS * PW);
        const int oy  = rem / PW;
        const int px  = rem % PW;
        const int iy0 = 2 * oy, ix0 = 4 * px;
        const float* base = sIn + g * IN;
        float* mid = sMid + g * MID;

        #pragma unroll 1
        for (int og = 0; og < 2; ++og) {
            float acc[2][4][5];
            #pragma unroll
            for (int oc = 0; oc < 5; ++oc) {
                const float bv = sB3[og * 5 + oc];
                #pragma unroll
                for (int dy = 0; dy < 2; ++dy)
                    #pragma unroll
                    for (int dx = 0; dx < 4; ++dx) acc[dy][dx][oc] = bv;
            }

            #pragma unroll 1
            for (int ic = 0; ic < 10; ++ic) {
                const float* rp = base + ic * IS * IS + iy0 * IS + ix0;
                float v[4][6];
                #pragma unroll
                for (int r = 0; r < 4; ++r)
                    #pragma unroll
                    for (int c = 0; c < 6; ++c) v[r][c] = rp[r * IS + c];

                const float* wp = sW3 + (og * 5) * 90 + ic * 9;
                #pragma unroll
                for (int ky = 0; ky < 3; ++ky)
                    #pragma unroll
                    for (int kx = 0; kx < 3; ++kx)
                        #pragma unroll
                        for (int oc = 0; oc < 5; ++oc) {
                            const float wv = wp[oc * 90 + ky * 3 + kx];
                            #pragma unroll
                            for (int dy = 0; dy < 2; ++dy)
                                #pragma unroll
                                for (int dx = 0; dx < 4; ++dx)
                                    acc[dy][dx][oc] += wv * v[ky + dy][kx + dx];
                        }
            }

            #pragma unroll
            for (int j = 0; j < 2; ++j) {
                const int ox = 2 * px + j;
                #pragma unroll
                for (int oc = 0; oc < 5; ++oc) {
                    float m = fmaxf(fmaxf(acc[0][2 * j][oc], acc[0][2 * j + 1][oc]),
                                    fmaxf(acc[1][2 * j][oc], acc[1][2 * j + 1][oc]));
                    mid[(og * 5 + oc) * (OS * OS) + oy * OS + ox] = fmaxf(m, 0.0f);
                }
            }
        }
    }
    __syncthreads();

    for (int item = threadIdx.x; item < G * 16; item += BD) {
        const int g   = item / 16;
        const int pix = item % 16;
        const int oy  = pix / 4, ox = pix % 4;
        const float* mid = sMid + g * MID;

        #pragma unroll 1
        for (int og = 0; og < 2; ++og) {
            float acc[2][2][5];
            #pragma unroll
            for (int oc = 0; oc < 5; ++oc) {
                const float bv = sB4[og * 5 + oc];
                acc[0][0][oc] = bv; acc[0][1][oc] = bv;
                acc[1][0][oc] = bv; acc[1][1][oc] = bv;
            }

            #pragma unroll 1
            for (int ic = 0; ic < 10; ++ic) {
                const float* rp = mid + ic * (OS * OS) + 2 * oy * OS + 2 * ox;
                float v[4][4];
                #pragma unroll
                for (int r = 0; r < 4; ++r)
                    #pragma unroll
                    for (int c = 0; c < 4; ++c) v[r][c] = rp[r * OS + c];

                const float* wp = sW4 + (og * 5) * 90 + ic * 9;
                #pragma unroll
                for (int ky = 0; ky < 3; ++ky)
                    #pragma unroll
                    for (int kx = 0; kx < 3; ++kx)
                        #pragma unroll
                        for (int oc = 0; oc < 5; ++oc) {
                            const float wv = wp[oc * 90 + ky * 3 + kx];
                            #pragma unroll
                            for (int dy = 0; dy < 2; ++dy)
                                #pragma unroll
                                for (int dx = 0; dx < 2; ++dx)
                                    acc[dy][dx][oc] += wv * v[ky + dy][kx + dx];
                        }
            }

            #pragma unroll
            for (int oc = 0; oc < 5; ++oc) {
                float m = fmaxf(fmaxf(acc[0][0][oc], acc[0][1][oc]),
                                fmaxf(acc[1][0][oc], acc[1][1][oc]));
                out[(size_t)(img0 + g) * 160 + (og * 5 + oc) * 16 + pix]
                    = fmaxf(m, 0.0f);
            }
        }
    }
}

// ---------------------------------------------------------------------------
// Double-buffered SGEMM-NT (FROZEN: dense TM=4/BD=128, xy TM=2/BD=256).
// ---------------------------------------------------------------------------
template<int TM, int BD, bool TANH, bool HASBIAS, bool DIAG>
__global__ __launch_bounds__(BD)
void gemmV(const float* __restrict__ A, const float* __restrict__ B,
           const float* __restrict__ bias, float* __restrict__ C,
           float* __restrict__ xxOut,
           int M, int N, int K,
           long long sA, long long sB, long long sC)
{
    constexpr int TN = 2;
    constexpr int TX = 32 / TN;
    constexpr int NLD = 512 / BD;
    __shared__ float As[32][36];
    __shared__ float Bs[32][36];

    const int tid = threadIdx.x;
    const int ty = tid / TX;
    const int tx = tid % TX;

    const int row0 = blockIdx.y * 32;
    const int col0 = blockIdx.x * 32;
    const float* Ab = A + blockIdx.z * sA + (size_t)row0 * K;
    const float* Bb = B + blockIdx.z * sB + (size_t)col0 * K;
    float* Cb = C + blockIdx.z * sC;

    float acc[TM][TN] = {};
    float4 pre[NLD];

    #pragma unroll
    for (int l = 0; l < NLD; ++l) {
        const int i = tid + l * BD;
        const int idx = i & 255;
        const float* src = ((i < 256) ? Ab : Bb)
                         + (size_t)(idx >> 3) * K + (idx & 7) * 4;
        pre[l] = *(const float4*)src;
    }

    for (int k0 = 0; k0 < K; k0 += 32) {
        #pragma unroll
        for (int l = 0; l < NLD; ++l) {
            const int i = tid + l * BD;
            const int idx = i & 255;
            const int r = idx >> 3;
            const int q = idx & 7;
            float* dst = (i < 256) ? &As[q * 4][r] : &Bs[q * 4][r];
            dst[0 * 36] = pre[l].x; dst[1 * 36] = pre[l].y;
            dst[2 * 36] = pre[l].z; dst[3 * 36] = pre[l].w;
        }
        __syncthreads();

        if (k0 + 32 < K) {
            #pragma unroll
            for (int l = 0; l < NLD; ++l) {
                const int i = tid + l * BD;
                const int idx = i & 255;
                const float* src = ((i < 256) ? Ab : Bb)
                                 + (size_t)(idx >> 3) * K + k0 + 32 + (idx & 7) * 4;
                pre[l] = *(const float4*)src;
            }
        }

        #pragma unroll
        for (int kk = 0; kk < 32; ++kk) {
            float a[TM], b[TN];
            if (TM == 4) {
                const float4 t = *(const float4*)&As[kk][ty * 4];
                a[0] = t.x; a[1] = t.y; a[2] = t.z; a[3] = t.w;
            } else {
                const float2 t = *(const float2*)&As[kk][ty * 2];
                a[0] = t.x; a[1] = t.y;
            }
            {
                const float2 t = *(const float2*)&Bs[kk][tx * 2];
                b[0] = t.x; b[1] = t.y;
            }
            #pragma unroll
            for (int i = 0; i < TM; ++i)
                #pragma unroll
                for (int j = 0; j < TN; ++j)
                    acc[i][j] += a[i] * b[j];
        }
        __syncthreads();
    }

    #pragma unroll
    for (int i = 0; i < TM; ++i) {
        const int gr = row0 + ty * TM + i;
        #pragma unroll
        for (int j = 0; j < TN; ++j) {
            const int gc = col0 + tx * TN + j;
            float v = acc[i][j];
            if (HASBIAS) v += bias[gc];
            if (TANH) v = tanhf(v);
            Cb[(size_t)gr * N + gc] = v;
            if (DIAG && gr == gc)
                xxOut[blockIdx.z * 128 + gr] = v;
        }
    }
}

// ---------------------------------------------------------------------------
// Fused softmax + message-pass + residual average (per-round recompute —
// measured faster than persisting K). Block: 8 rows, 160 threads.
// ---------------------------------------------------------------------------
__global__ void mix_avg_sm_kernel(const float* __restrict__ xy,
                                  const float* __restrict__ xx,
                                  const float* __restrict__ sigma,
                                  const float* __restrict__ z,
                                  float* __restrict__ out)
{
    const int b  = blockIdx.y;
    const int n0 = blockIdx.x * 8;
    const int t  = threadIdx.x;

    __shared__ float sK[8][128];
    __shared__ float sSum[8];

    const float inv_s = 1.0f / sigma[0];
    const float* xyr = xy + ((size_t)b * 128 + n0) * 128;
    const float* xxb = xx + b * 128;

    for (int i = t; i < 8 * 128; i += 160) {
        const int m = i & 127;
        sK[i >> 7][m] = (2.0f * xyr[i] - xxb[m]) * inv_s;
    }
    __syncthreads();

    if (t < 128) {
        const int r = t >> 4;
        const int s = t & 15;
        float mx = -3.0e38f;
        #pragma unroll
        for (int m = s; m < 128; m += 16) mx = fmaxf(mx, sK[r][m]);
        #pragma unroll
        for (int o = 8; o > 0; o >>= 1)
            mx = fmaxf(mx, __shfl_down_sync(0xFFFFFFFFu, mx, o, 16));
        mx = __shfl_sync(0xFFFFFFFFu, mx, 0, 16);

        float sum = 0.0f;
        #pragma unroll
        for (int m = s; m < 128; m += 16) {
            const float e = expf(sK[r][m] - mx);
            sK[r][m] = e;
            sum += e;
        }
        #pragma unroll
        for (int o = 8; o > 0; o >>= 1)
            sum += __shfl_down_sync(0xFFFFFFFFu, sum, o, 16);
        if (s == 0) sSum[r] = sum;
    }
    __syncthreads();

    if (t < 128) {
        const int r = t >> 4;
        const int s = t & 15;
        const float sum = sSum[r];
        #pragma unroll
        for (int m = s; m < 128; m += 16) sK[r][m] = sK[r][m] / sum;
    }
    __syncthreads();

    const float* zb = z + (size_t)b * 128 * 160;
    float acc[8] = {};
    #pragma unroll 4
    for (int m = 0; m < 128; ++m) {
        const float zv = zb[(size_t)m * 160 + t];
        #pragma unroll
        for (int j = 0; j < 8; ++j) acc[j] += sK[j][m] * zv;
    }
    #pragma unroll
    for (int j = 0; j < 8; ++j)
        out[((size_t)b * 128 + n0 + j) * 160 + t] =
            0.5f * (acc[j] + zb[(size_t)(n0 + j) * 160 + t]);
}

// out[b] = exp( sum_d max_n(H6[b,n,d]) * Wc[d] + bc )
__global__ void final_kernel(const float* __restrict__ H6,
                             const float* __restrict__ Wc,
                             const float* __restrict__ bc,
                             float* __restrict__ out)
{
    const int b = blockIdx.x;
    const int t = threadIdx.x;
    float m = -3.0e38f;
    for (int n = 0; n < 128; ++n)
        m = fmaxf(m, H6[((size_t)b * 128 + n) * 160 + t]);
    float s = m * Wc[t];
    #pragma unroll
    for (int o = 16; o > 0; o >>= 1)
        s += __shfl_down_sync(0xFFFFFFFFu, s, o);
    __shared__ float red[5];
    if ((t & 31) == 0) red[t >> 5] = s;
    __syncthreads();
    if (t == 0) {
        float tot = red[0] + red[1] + red[2] + red[3] + red[4];
        out[b] = expf(tot + bc[0]);
    }
}

// ---------------------------------------------------------------------------
// Host launcher
// ---------------------------------------------------------------------------
extern "C" void kernel_launch(void* const* d_in, const int* in_sizes, int n_in,
                              void* d_out, int out_size)
{
    const float* H     = (const float*)d_in[0];
    const float* w1    = (const float*)d_in[1];
    const float* b1    = (const float*)d_in[2];
    const float* w2    = (const float*)d_in[3];
    const float* b2    = (const float*)d_in[4];
    const float* w3    = (const float*)d_in[5];
    const float* b3    = (const float*)d_in[6];
    const float* w4    = (const float*)d_in[7];
    const float* b4    = (const float*)d_in[8];
    const float* Wdk1  = (const float*)d_in[9];
    const float* bdk1  = (const float*)d_in[10];
    const float* Wdk2  = (const float*)d_in[11];
    const float* bdk2  = (const float*)d_in[12];
    const float* Wt1   = (const float*)d_in[13];
    const float* bt1   = (const float*)d_in[14];
    const float* Wt2   = (const float*)d_in[15];
    const float* bt2   = (const float*)d_in[16];
    const float* Wt3   = (const float*)d_in[17];
    const float* bt3   = (const float*)d_in[18];
    const float* sigma = (const float*)d_in[19];
    const float* Wc    = (const float*)d_in[20];
    const float* bc    = (const float*)d_in[21];

    float *p1, *p2, *hf, *dk1, *dkf, *xx, *xy, *avg, *h2, *h4, *h6;
    cudaGetSymbolAddress((void**)&p1,  g_P1);
    cudaGetSymbolAddress((void**)&p2,  g_P2);
    cudaGetSymbolAddress((void**)&hf,  g_Hf);
    cudaGetSymbolAddress((void**)&dk1, g_dk1);
    cudaGetSymbolAddress((void**)&dkf, g_dkf);
    cudaGetSymbolAddress((void**)&xx,  g_xx);
    cudaGetSymbolAddress((void**)&xy,  g_XY);
    cudaGetSymbolAddress((void**)&avg, g_avg);
    cudaGetSymbolAddress((void**)&h2,  g_H2);
    cudaGetSymbolAddress((void**)&h4,  g_H4);
    cudaGetSymbolAddress((void**)&h6,  g_H6);

    const size_t smem1 = (52 * 100 + 90 + 10) * sizeof(float);               // 21.2 KB
    const size_t smem2 = (10 * 26 * 49 + 900 + 10) * sizeof(float);          // 54.6 KB
    const size_t smemf = (2 * 10 * 23 * 23 + 900 + 10 + 2 * 1000 + 900 + 10)
                         * sizeof(float);                                     // 57.6 KB
    cudaFuncSetAttribute(conv_pool_rows<10, 49, 160>,
                         cudaFuncAttributeMaxDynamicSharedMemorySize, (int)smem2);
    cudaFuncSetAttribute(conv34_fused<2, 128>,
                         cudaFuncAttributeMaxDynamicSharedMemorySize, (int)smemf);

    // ---- Conv stack ----
    conv1_rows<<<dim3(NIMG, 2), 160, smem1>>>(H, w1, b1, p1);
    conv_pool_rows<10, 49, 160><<<dim3(NIMG, 2), 160, smem2>>>(p1, w2, b2, p2);
    conv34_fused<2, 128><<<NIMG / 2, 128, smemf>>>(p2, w3, b3, w4, b4, hf);

    // ---- Deep-kernel MLP ----
    gemmV<4, 128, true, true, false><<<dim3(8, 32), 128>>>(
        hf, Wdk1, bdk1, dk1, nullptr, 1024, 256, 160, 0, 0, 0);
    gemmV<4, 128, true, true, false><<<dim3(16, 32), 128>>>(
        dk1, Wdk2, bdk2, dkf, nullptr, 1024, 512, 256, 0, 0, 0);

    // ---- Gram matrix xy (+ diagonal -> xx); softmax fused into mix ----
    gemmV<2, 256, false, false, true><<<dim3(4, 4, 8), 256>>>(
        dkf, dkf, nullptr, xy, xx, 128, 128, 512,
        128LL * 512, 128LL * 512, 128LL * 128);

    dim3 mixg(16, 8);

    // ---- Round 1 ----
    mix_avg_sm_kernel<<<mixg, 160>>>(xy, xx, sigma, hf, avg);
    gemmV<4, 128, true, true, false><<<dim3(5, 32), 128>>>(
        avg, Wt1, bt1, h2, nullptr, 1024, 160, 160, 0, 0, 0);

    // ---- Round 2 ----
    mix_avg_sm_kernel<<<mixg, 160>>>(xy, xx, sigma, h2, avg);
    gemmV<4, 128, true, true, false><<<dim3(5, 32), 128>>>(
        avg, Wt2, bt2, h4, nullptr, 1024, 160, 160, 0, 0, 0);

    // ---- Round 3 ----
    mix_avg_sm_kernel<<<mixg, 160>>>(xy, xx, sigma, h4, avg);
    gemmV<4, 128, true, true, false><<<dim3(5, 32), 128>>>(
        avg, Wt3, bt3, h6, nullptr, 1024, 160, 160, 0, 0, 0);

    // ---- Finish ----
    final_kernel<<<8, 160>>>(h6, Wc, bc, (float*)d_out);
}